// round 17
// baseline (speedup 1.0000x reference)
#include <cuda_runtime.h>
#include <math.h>

#define BATCH 64
#define SEQ   512
#define EMB   512
#define HID   1024
#define BH    (BATCH * HID)        // 65536
#define SBH   (SEQ * BH)           // 33554432
#define KSLICES 8
#define NBLOCKS 128                // 16 h-tiles (64h) x 8 k-slices (128k)

#define ASTRIDE 12                 // warp-private k-major staging row (floats)
#define PAR (KSLICES * BH)         // one parity of partials (floats)
#define RNN_SMEM ((128 * 64 + 8 * 128 * ASTRIDE) * 4)   // 32KB Ws + 48KB Asw

typedef unsigned long long u64;

// W_aa K-split partials, parity double-buffered: [2][KSLICES][BATCH][HID] = 4 MB
__device__ float g_partial[2 * PAR];
// Counters: ca[g] at g*64, cp[g] at 512+g*64 (256B apart). Targets 128*s
// (8 warps x 16 CTAs arrive per group per step). Zeroed per launch.
__device__ unsigned g_sync[1024];

// ---------------- packed fp32x2 helpers (sm_103a) ---------------------------
__device__ __forceinline__ u64 pkdup(float x) {
    u64 r; asm("mov.b64 %0, {%1, %1};" : "=l"(r) : "f"(x)); return r;
}
__device__ __forceinline__ void fma2(u64& d, u64 a, u64 b) {
    asm("fma.rn.f32x2 %0, %1, %2, %0;" : "+l"(d) : "l"(a), "l"(b));
}
__device__ __forceinline__ float2 un2(u64 v) {
    float2 f; asm("mov.b64 {%0, %1}, %2;" : "=f"(f.x), "=f"(f.y) : "l"(v));
    return f;
}
__device__ __forceinline__ unsigned ldacq(const unsigned* p) {
    unsigned v;
    asm volatile("ld.acquire.gpu.global.u32 %0, [%1];" : "=r"(v) : "l"(p));
    return v;
}
__device__ __forceinline__ void redrel(unsigned* p) {
    asm volatile("red.release.gpu.global.add.u32 [%0], %1;"
                 :: "l"(p), "r"(1u) : "memory");
}

// ---------------------------------------------------------------------------
// Kernel 1: xproj[s][b][h] = sum_e X[b][s][e] * Wax[h][e] + ba[h]
// (unchanged proven GEMM; writes into outs, consumed in place by the scan)
// ---------------------------------------------------------------------------
__global__ __launch_bounds__(256) void xproj_kernel(
    const float* __restrict__ X, const float* __restrict__ Wax,
    const float* __restrict__ ba, float* __restrict__ out)
{
    __shared__ float As[16][128];
    __shared__ float Bs[16][128];

    const int tid = threadIdx.x;
    const int r0 = blockIdx.x * 128;
    const int h0 = blockIdx.y * 128;

    const int lr = tid >> 1;
    const int lk = (tid & 1) * 8;
    const int r  = r0 + lr;
    const float* Aptr = X + (size_t)(r & (BATCH - 1)) * (SEQ * EMB)
                          + (size_t)(r >> 6) * EMB + lk;
    const float* Bptr = Wax + (size_t)(h0 + lr) * EMB + lk;

    const int tm0 = (tid >> 4) * 4;
    const int tn0 = (tid & 15) * 4;

    u64 acc[8][4];
#pragma unroll
    for (int i = 0; i < 8; i++)
#pragma unroll
        for (int p = 0; p < 4; p++) acc[i][p] = 0ull;

    for (int k0 = 0; k0 < EMB; k0 += 16) {
        float4 a0 = *(const float4*)(Aptr + k0);
        float4 a1 = *(const float4*)(Aptr + k0 + 4);
        float4 b0 = *(const float4*)(Bptr + k0);
        float4 b1 = *(const float4*)(Bptr + k0 + 4);
        As[lk + 0][lr] = a0.x; As[lk + 1][lr] = a0.y;
        As[lk + 2][lr] = a0.z; As[lk + 3][lr] = a0.w;
        As[lk + 4][lr] = a1.x; As[lk + 5][lr] = a1.y;
        As[lk + 6][lr] = a1.z; As[lk + 7][lr] = a1.w;
        Bs[lk + 0][lr] = b0.x; Bs[lk + 1][lr] = b0.y;
        Bs[lk + 2][lr] = b0.z; Bs[lk + 3][lr] = b0.w;
        Bs[lk + 4][lr] = b1.x; Bs[lk + 5][lr] = b1.y;
        Bs[lk + 6][lr] = b1.z; Bs[lk + 7][lr] = b1.w;
        __syncthreads();

#pragma unroll
        for (int k = 0; k < 16; k++) {
            float4 av0 = *(const float4*)&As[k][tm0];
            float4 av1 = *(const float4*)&As[k][tm0 + 64];
            ulonglong2 wA = *(const ulonglong2*)&Bs[k][tn0];
            ulonglong2 wB = *(const ulonglong2*)&Bs[k][tn0 + 64];
            float ar[8] = {av0.x, av0.y, av0.z, av0.w, av1.x, av1.y, av1.z, av1.w};
#pragma unroll
            for (int i = 0; i < 8; i++) {
                u64 ai = pkdup(ar[i]);
                fma2(acc[i][0], ai, wA.x);
                fma2(acc[i][1], ai, wA.y);
                fma2(acc[i][2], ai, wB.x);
                fma2(acc[i][3], ai, wB.y);
            }
        }
        __syncthreads();
    }

    float bav[8];
#pragma unroll
    for (int j = 0; j < 4; j++) {
        bav[j]     = ba[h0 + tn0 + j];
        bav[4 + j] = ba[h0 + tn0 + 64 + j];
    }
#pragma unroll
    for (int gi = 0; gi < 2; gi++) {
#pragma unroll
        for (int ii = 0; ii < 4; ii++) {
            int i = gi * 4 + ii;
            int row = r0 + tm0 + gi * 64 + ii;
            float* o = out + (size_t)row * HID + h0;
            float2 p0 = un2(acc[i][0]), p1 = un2(acc[i][1]);
            float2 p2 = un2(acc[i][2]), p3 = un2(acc[i][3]);
            *(float4*)(o + tn0)      = make_float4(p0.x + bav[0], p0.y + bav[1],
                                                   p1.x + bav[2], p1.y + bav[3]);
            *(float4*)(o + tn0 + 64) = make_float4(p2.x + bav[4], p2.y + bav[5],
                                                   p3.x + bav[6], p3.y + bav[7]);
        }
    }
}

// ---------------------------------------------------------------------------
// Kernel 2: persistent recurrence — R11 skeleton, shortened chain.
// CTA bi: h-tile ht=bi>>3 (64 h), k-slice ks=bi&7 (128 k), group g=ht>>1.
// Per step s>=1 (2 __syncthreads total):
//   tid0 polls ca[ks] >= 128s; B1
//   per-warp: stage own b-octet a_{s-1}[.][k-slice] -> private smem; compute
//   acc[4bp][2h] over 128k (f32x2); lagging overwrite check ca[g]>=128(s-1);
//   STG partials[parity s&1]; syncwarp; lane0 redrel(cp[g]);
//   tid0 polls cp[g] >= 128s; B2
//   phase2: tanh(xp + sum8 partials[parity]); STG outs[s]; syncwarp;
//   lane0 redrel(ca[g]).
// Per-warp release after __syncwarp is a valid release (warp barrier gives
// memory ordering; cumulativity carries all lanes' prior STGs).
// ---------------------------------------------------------------------------
__global__ __launch_bounds__(256, 1) void rnn_persistent(
    const float* __restrict__ Waa, float* __restrict__ outs, int write_hidden)
{
    extern __shared__ float sm[];
    float* Ws = sm;                           // [128][64]

    const int tid = threadIdx.x;
    const int bi  = blockIdx.x;
    const int ht  = bi >> 3;                  // 0..15
    const int ks  = bi & 7;                   // 0..7
    const int g   = ht >> 1;                  // 0..7
    const int h0  = ht * 64;
    const int k0  = ks * 128;
    const int w   = tid >> 5;                 // warp = b-octet 0..7
    const int l   = tid & 31;

    float* Asw = sm + 128 * 64 + w * (128 * ASTRIDE);  // warp-private strip

    unsigned* ca_own = g_sync + g * 64;
    unsigned* ca_ks  = g_sync + ks * 64;
    unsigned* cp_own = g_sync + 512 + g * 64;

    // Load W_aa slice once: Ws[k][h] = Waa[h0+h][k0+k]
    {
        const int h  = tid & 63;
        const int kg = tid >> 6;
        const float* wrow = Waa + (size_t)(h0 + h) * HID + k0 + kg * 32;
#pragma unroll
        for (int j = 0; j < 8; j++) {
            float4 wv = *(const float4*)(wrow + j * 4);
            int k = kg * 32 + j * 4;
            Ws[(k + 0) * 64 + h] = wv.x; Ws[(k + 1) * 64 + h] = wv.y;
            Ws[(k + 2) * 64 + h] = wv.z; Ws[(k + 3) * 64 + h] = wv.w;
        }
    }
    __syncthreads();

    const int hh  = 2 * l;                    // h-pair within 64
    const int sbp = l & 7;                    // staging b within octet
    const int skb = (l >> 3) * 4;             // staging k base
    // phase2 map: e = cg*256 + tid -> (b = e>>6, h = 128g + 2*(e&63))
    const int cg = ((ht & 1) << 3) | ks;      // CTA index within group
    const int e  = cg * 256 + tid;            // 0..4095
    const size_t p2off = (size_t)(e >> 6) * HID + (size_t)g * 128 + 2 * (e & 63);

    for (int s = 0; s < SEQ; s++) {
        // prefetch own xproj element (only this thread ever writes it)
        float2 xp = *(const float2*)(outs + (size_t)s * BH + p2off);
        const float* ppart = g_partial + (size_t)(s & 1) * PAR + p2off;

        if (s > 0) {
            const unsigned t = 128u * (unsigned)s;
            if (tid == 0) { while (ldacq(ca_ks) < t) { } }
            __syncthreads();                                   // B1

            // ---- stage a_{s-1}[own 8 rows][128 k] into warp-private smem
            const float* src = outs + (size_t)(s - 1) * BH
                             + (size_t)(8 * w + sbp) * HID + k0 + skb;
#pragma unroll
            for (int j = 0; j < 8; j++) {
                float4 v = __ldcg((const float4*)(src + j * 16));
                int k = skb + j * 16;
                Asw[(k + 0) * ASTRIDE + sbp] = v.x;
                Asw[(k + 1) * ASTRIDE + sbp] = v.y;
                Asw[(k + 2) * ASTRIDE + sbp] = v.z;
                Asw[(k + 3) * ASTRIDE + sbp] = v.w;
            }
            __syncwarp();

            // ---- compute acc[4 b-pairs][2 h] over 128 k (R11 inner loop)
            u64 acc[4][2];
#pragma unroll
            for (int i = 0; i < 4; i++) { acc[i][0] = 0ull; acc[i][1] = 0ull; }

#pragma unroll 8
            for (int k = 0; k < 128; k++) {
                ulonglong2 aA = *(const ulonglong2*)(Asw + k * ASTRIDE);
                ulonglong2 aB = *(const ulonglong2*)(Asw + k * ASTRIDE + 4);
                float2 wv = *(const float2*)(Ws + k * 64 + hh);
                u64 w0 = pkdup(wv.x);
                u64 w1 = pkdup(wv.y);
                fma2(acc[0][0], aA.x, w0); fma2(acc[0][1], aA.x, w1);
                fma2(acc[1][0], aA.y, w0); fma2(acc[1][1], aA.y, w1);
                fma2(acc[2][0], aB.x, w0); fma2(acc[2][1], aB.x, w1);
                fma2(acc[3][0], aB.y, w0); fma2(acc[3][1], aB.y, w1);
            }

            // ---- lagging overwrite guard for parity buffer (off crit path):
            // phase2(s-2) readers of this parity finished before ca hit
            // 128*(s-1); normally already satisfied -> single acquire load.
            if (s > 1 && l == 0) {
                const unsigned tg = 128u * (unsigned)(s - 1);
                while (ldacq(ca_own) < tg) { }
            }
            __syncwarp();

            // ---- write partials: g_partial[s&1][ks][8w+row][h0+hh..+1]
            float* gp = g_partial + (size_t)(s & 1) * PAR + (size_t)ks * BH
                      + (size_t)(8 * w) * HID + h0 + hh;
#pragma unroll
            for (int bp = 0; bp < 4; bp++) {
                float2 ev = un2(acc[bp][0]);
                float2 ov = un2(acc[bp][1]);
                *(float2*)(gp + (size_t)(2 * bp)     * HID) = make_float2(ev.x, ov.x);
                *(float2*)(gp + (size_t)(2 * bp + 1) * HID) = make_float2(ev.y, ov.y);
            }
            __syncwarp();
            if (l == 0) redrel(cp_own);                        // per-warp arrive

            if (tid == 0) { while (ldacq(cp_own) < t) { } }
            __syncthreads();                                   // B2
        }

        // ---- phase2: one float2 per thread, tanh(xp + sum8 partials)
        {
            float2 v = xp;
            if (s > 0) {
#pragma unroll
                for (int p = 0; p < KSLICES; p++) {
                    float2 q = __ldcg((const float2*)(ppart + (size_t)p * BH));
                    v.x += q.x; v.y += q.y;
                }
            }
            v.x = tanhf(v.x); v.y = tanhf(v.y);
            *(float2*)(outs + (size_t)s * BH + p2off) = v;
            if (write_hidden && s == SEQ - 1)
                *(float2*)(outs + (size_t)SBH + p2off) = v;
        }
        __syncwarp();
        if (l == 0) redrel(ca_own);                            // per-warp arrive
    }
}

// ---------------------------------------------------------------------------
// Launch. Inputs: X [B,S,E] f32, W_ax [H,E] f32, W_aa [H,H] f32, b_a [H] f32.
// Output: outputs [S,B,H] then hidden [B,H].
// ---------------------------------------------------------------------------
extern "C" void kernel_launch(void* const* d_in, const int* in_sizes, int n_in,
                              void* d_out, int out_size) {
    (void)in_sizes; (void)n_in;
    const float* X   = (const float*)d_in[0];
    const float* Wax = (const float*)d_in[1];
    const float* Waa = (const float*)d_in[2];
    const float* ba  = (const float*)d_in[3];
    float* out = (float*)d_out;

    cudaFuncSetAttribute(rnn_persistent,
                         cudaFuncAttributeMaxDynamicSharedMemorySize, RNN_SMEM);

    void* sp = nullptr;
    cudaGetSymbolAddress(&sp, g_sync);
    cudaMemsetAsync(sp, 0, 1024 * sizeof(unsigned), 0);

    dim3 g1((SEQ * BATCH) / 128, HID / 128);
    xproj_kernel<<<g1, 256>>>(X, Wax, ba, out);

    int write_hidden = (out_size >= (int)(SBH + BH)) ? 1 : 0;
    rnn_persistent<<<NBLOCKS, 256, RNN_SMEM>>>(Waa, out, write_hidden);
}